// round 1
// baseline (speedup 1.0000x reference)
#include <cuda_runtime.h>
#include <stdint.h>

// Problem dims (fixed by the reference)
#define BATCH 1024
#define M     2048
#define R     8192

#define MAX_E 32   // max nnz per reaction column of E (mean ~4.1)
#define MAX_S 64   // max nnz per metabolite row of S (mean ~16.4)

// Scratch (device globals — no allocation allowed)
__device__ int e_cnt[R];
__device__ int s_cnt[M];
__device__ unsigned short e_list[MAX_E * R];   // [slot][reaction]  pack: (i<<1)|(exp-1)
__device__ unsigned short s_list[MAX_S * M];   // [slot][metabolite] pack: (j<<2)|code, code: -2->0,-1->1,1->2,2->3

// ---------------------------------------------------------------------------
__global__ void reset_kernel() {
    int t = blockIdx.x * blockDim.x + threadIdx.x;
    for (int j = t; j < R; j += gridDim.x * blockDim.x) e_cnt[j] = 0;
    for (int i = t; i < M; i += gridDim.x * blockDim.x) s_cnt[i] = 0;
}

// ---------------------------------------------------------------------------
// Scan dense E and S (row-major [M, R]) with int4 loads; build packed lists.
__global__ void sparsify_kernel(const int* __restrict__ E, const int* __restrict__ S) {
    int t = blockIdx.x * blockDim.x + threadIdx.x;          // one int4 per thread
    const int total4 = (M * R) / 4;
    if (t >= total4) return;
    int base = t * 4;
    int i  = base >> 13;          // / R
    int j0 = base & (R - 1);      // % R   (same row for all 4 lanes, R % 4 == 0)

    int4 ev = __ldg(reinterpret_cast<const int4*>(E) + t);
    int4 sv = __ldg(reinterpret_cast<const int4*>(S) + t);

    int evs[4] = {ev.x, ev.y, ev.z, ev.w};
    int svs[4] = {sv.x, sv.y, sv.z, sv.w};

    #pragma unroll
    for (int u = 0; u < 4; ++u) {
        int j = j0 + u;
        int e = evs[u];
        if (e != 0) {
            int p = atomicAdd(&e_cnt[j], 1);
            if (p < MAX_E)
                e_list[p * R + j] = (unsigned short)((i << 1) | (e - 1));
        }
        int s = svs[u];
        if (s != 0) {
            int code = (s < 0) ? (s + 2) : (s + 1);   // -2->0, -1->1, 1->2, 2->3
            int p = atomicAdd(&s_cnt[i], 1);
            if (p < MAX_S)
                s_list[p * M + i] = (unsigned short)((j << 2) | code);
        }
    }
}

// ---------------------------------------------------------------------------
// One CTA per batch row: conc row -> smem, all 8192 rates -> smem, then
// gather the stoichiometric sum per metabolite. No global atomics.
__global__ __launch_bounds__(256) void compute_kernel(const float* __restrict__ conc,
                                                      const float* __restrict__ krate,
                                                      float* __restrict__ out) {
    __shared__ float sc[M];    // 8 KB  : concentration row
    __shared__ float sv[R];    // 32 KB : reaction rates v
    const int b   = blockIdx.x;
    const int tid = threadIdx.x;

    const float4* crow = reinterpret_cast<const float4*>(conc + (size_t)b * M);
    #pragma unroll
    for (int u = 0; u < M / 4 / 256; ++u) {
        int idx = tid + u * 256;
        float4 v = crow[idx];
        sc[idx * 4 + 0] = v.x; sc[idx * 4 + 1] = v.y;
        sc[idx * 4 + 2] = v.z; sc[idx * 4 + 3] = v.w;
    }
    __syncthreads();

    // Rates: v_j = k_j * prod_i c_i^{E_ij}  (E in {1,2} -> c or c*c)
    #pragma unroll 4
    for (int j = tid; j < R; j += 256) {
        int cnt = e_cnt[j];
        cnt = cnt < MAX_E ? cnt : MAX_E;
        float p = __ldg(&krate[j]);
        for (int t = 0; t < cnt; ++t) {
            unsigned short pk = e_list[t * R + j];
            float c = sc[pk >> 1];
            p *= (pk & 1) ? c * c : c;
        }
        sv[j] = p;
    }
    __syncthreads();

    // dXdt[b,i] = sum_j v_j * S_ij
    float* orow = out + (size_t)b * M;
    #pragma unroll 2
    for (int i = tid; i < M; i += 256) {
        int cnt = s_cnt[i];
        cnt = cnt < MAX_S ? cnt : MAX_S;
        float acc = 0.0f;
        for (int t = 0; t < cnt; ++t) {
            unsigned short pk = s_list[t * M + i];
            int code = pk & 3;
            float coeff = (float)(code - (code < 2 ? 2 : 1));  // {-2,-1,1,2}
            acc += sv[pk >> 2] * coeff;
        }
        orow[i] = acc;
    }
}

// ---------------------------------------------------------------------------
extern "C" void kernel_launch(void* const* d_in, const int* in_sizes, int n_in,
                              void* d_out, int out_size) {
    const float* conc = (const float*)d_in[0];   // [B, M]
    const int*   E    = (const int*)d_in[1];     // [M, R]
    const int*   S    = (const int*)d_in[2];     // [M, R]
    const float* k    = (const float*)d_in[3];   // [R]
    float*       out  = (float*)d_out;           // [B, M]

    reset_kernel<<<8, 256>>>();

    const int total4 = (M * R) / 4;
    sparsify_kernel<<<(total4 + 255) / 256, 256>>>(E, S);

    compute_kernel<<<BATCH, 256>>>(conc, k, out);
}

// round 4
// speedup vs baseline: 1.6342x; 1.6342x over previous
#include <cuda_runtime.h>
#include <stdint.h>

// Problem dims (fixed by the reference)
#define BATCH 1024
#define M     2048
#define R     8192
#define NB    4            // batch rows per CTA
#define NT    512          // threads per CTA (compute kernel)

#define MAX_E 32   // max nnz per reaction column of E (mean ~4.1, Binom tail ~0 at 32)
#define MAX_S 64   // max nnz per metabolite row of S (mean ~16.4)

// Scratch (device globals — no allocation allowed)
__device__ int e_cnt[R];
__device__ int s_cnt[M];
__device__ unsigned short e_list[MAX_E * R];   // [slot][reaction]  pack: (i<<1)|(exp-1)
__device__ unsigned short s_list[MAX_S * M];   // [slot][metabolite] pack: (j<<2)|code, code: -2->0,-1->1,1->2,2->3

// ---------------------------------------------------------------------------
__global__ void reset_kernel() {
    int t = blockIdx.x * blockDim.x + threadIdx.x;
    if (t < R) e_cnt[t] = 0;
    if (t < M) s_cnt[t] = 0;
}

// ---------------------------------------------------------------------------
// Scan dense E and S (row-major [M, R]) with int4 loads; build packed lists.
__global__ void sparsify_kernel(const int* __restrict__ E, const int* __restrict__ S) {
    int t = blockIdx.x * blockDim.x + threadIdx.x;          // one int4 per thread
    const int total4 = (M * R) / 4;
    if (t >= total4) return;
    int base = t * 4;
    int i  = base >> 13;          // / R
    int j0 = base & (R - 1);      // % R   (row-aligned, R % 4 == 0)

    int4 ev = __ldg(reinterpret_cast<const int4*>(E) + t);
    int4 sv = __ldg(reinterpret_cast<const int4*>(S) + t);

    int evs[4] = {ev.x, ev.y, ev.z, ev.w};
    int svs[4] = {sv.x, sv.y, sv.z, sv.w};

    #pragma unroll
    for (int u = 0; u < 4; ++u) {
        int j = j0 + u;
        int e = evs[u];
        if (e != 0) {
            int p = atomicAdd(&e_cnt[j], 1);
            if (p < MAX_E)
                e_list[p * R + j] = (unsigned short)((i << 1) | (e - 1));
        }
        int s = svs[u];
        if (s != 0) {
            int code = (s < 0) ? (s + 2) : (s + 1);   // -2->0, -1->1, 1->2, 2->3
            int p = atomicAdd(&s_cnt[i], 1);
            if (p < MAX_S)
                s_list[p * M + i] = (unsigned short)((j << 2) | code);
        }
    }
}

// ---------------------------------------------------------------------------
// One CTA per NB=4 batch rows. conc tile and rate tile are stored interleaved
// as float4 {b0,b1,b2,b3} so every list entry costs ONE LDS.128 for 4 rows.
// smem: sc4[M] (32 KB) + sv4[R] (128 KB) = 160 KB dynamic.
__global__ __launch_bounds__(NT, 1) void compute_kernel(const float* __restrict__ conc,
                                                        const float* __restrict__ krate,
                                                        float* __restrict__ out) {
    extern __shared__ float4 smem4[];
    float4* sc4 = smem4;        // [M]
    float4* sv4 = smem4 + M;    // [R]

    const int b0  = blockIdx.x * NB;
    const int tid = threadIdx.x;

    const float* c0 = conc + (size_t)(b0 + 0) * M;
    const float* c1 = conc + (size_t)(b0 + 1) * M;
    const float* c2 = conc + (size_t)(b0 + 2) * M;
    const float* c3 = conc + (size_t)(b0 + 3) * M;

    #pragma unroll
    for (int u = 0; u < M / NT; ++u) {
        int m = tid + u * NT;
        float4 v;
        v.x = __ldg(&c0[m]); v.y = __ldg(&c1[m]);
        v.z = __ldg(&c2[m]); v.w = __ldg(&c3[m]);
        sc4[m] = v;
    }
    __syncthreads();

    // Rates: v[b,j] = k_j * prod_i c[b,i]^{E_ij}  (E in {1,2} -> c or c*c)
    #pragma unroll 2
    for (int j = tid; j < R; j += NT) {
        int cnt = e_cnt[j];
        cnt = cnt < MAX_E ? cnt : MAX_E;
        float kj = __ldg(&krate[j]);
        float4 p = make_float4(kj, kj, kj, kj);
        for (int t = 0; t < cnt; ++t) {
            unsigned short pk = e_list[t * R + j];
            float4 c = sc4[pk >> 1];
            if (pk & 1) { c.x *= c.x; c.y *= c.y; c.z *= c.z; c.w *= c.w; }
            p.x *= c.x; p.y *= c.y; p.z *= c.z; p.w *= c.w;
        }
        sv4[j] = p;
    }
    __syncthreads();

    // dXdt[b,i] = sum_j v[b,j] * S_ij
    float* o0 = out + (size_t)(b0 + 0) * M;
    float* o1 = out + (size_t)(b0 + 1) * M;
    float* o2 = out + (size_t)(b0 + 2) * M;
    float* o3 = out + (size_t)(b0 + 3) * M;

    #pragma unroll
    for (int u = 0; u < M / NT; ++u) {
        int i = tid + u * NT;
        int cnt = s_cnt[i];
        cnt = cnt < MAX_S ? cnt : MAX_S;
        float4 acc = make_float4(0.f, 0.f, 0.f, 0.f);
        for (int t = 0; t < cnt; ++t) {
            unsigned short pk = s_list[t * M + i];
            int code = pk & 3;
            float coeff = (float)(code - (code < 2 ? 2 : 1));  // {-2,-1,1,2}
            float4 v = sv4[pk >> 2];
            acc.x += v.x * coeff; acc.y += v.y * coeff;
            acc.z += v.z * coeff; acc.w += v.w * coeff;
        }
        o0[i] = acc.x; o1[i] = acc.y; o2[i] = acc.z; o3[i] = acc.w;
    }
}

// ---------------------------------------------------------------------------
extern "C" void kernel_launch(void* const* d_in, const int* in_sizes, int n_in,
                              void* d_out, int out_size) {
    const float* conc = (const float*)d_in[0];   // [B, M]
    const int*   E    = (const int*)d_in[1];     // [M, R]
    const int*   S    = (const int*)d_in[2];     // [M, R]
    const float* k    = (const float*)d_in[3];   // [R]
    float*       out  = (float*)d_out;           // [B, M]

    static_assert(BATCH % NB == 0, "");

    reset_kernel<<<(R + 255) / 256, 256>>>();

    const int total4 = (M * R) / 4;
    sparsify_kernel<<<(total4 + 255) / 256, 256>>>(E, S);

    const int smem_bytes = (M + R) * sizeof(float4);   // 160 KB
    cudaFuncSetAttribute(compute_kernel, cudaFuncAttributeMaxDynamicSharedMemorySize, smem_bytes);
    compute_kernel<<<BATCH / NB, NT, smem_bytes>>>(conc, k, out);
}

// round 9
// speedup vs baseline: 2.0074x; 1.2283x over previous
#include <cuda_runtime.h>
#include <stdint.h>

// Problem dims (fixed by the reference)
#define BATCH 1024
#define M     2048
#define R     8192
#define NB    4            // batch rows per CTA
#define NT    512          // threads per CTA (compute kernel)

#define MAX_E 32   // max nnz per reaction column of E (mean ~4.1)
#define MAX_S 64   // max nnz per metabolite row of S (mean ~16.4)

// Sentinels: unwritten slots act as no-ops in the compute loops.
//  E entry pack: (i<<1)|(exp-1). Sentinel -> i = M (dummy conc = 1.0), exp bit 0.
//  S entry pack: (j<<2)|code, code: -2->0,-1->1,1->2,2->3. Sentinel -> j = R (dummy v = 0), code 2 (coeff +1).
#define E_SENT 0x10001000u   // two packed sentinel ushorts (M<<1 = 0x1000)
#define S_SENT 0x80028002u   // two packed sentinel ushorts ((R<<2)|2 = 0x8002)

// Scratch (device globals — no allocation allowed)
__device__ int e_cnt[R];
__device__ int s_cnt[M];
__device__ ushort4 e_q[(MAX_E / 4) * R];   // quad q of column j at e_q[q*R + j]
__device__ uint4   s_q8[(MAX_S / 8) * M];  // octet g of row i at s_q8[g*M + i] (8 packed ushorts)

#define E_WORDS ((MAX_E * R) / 2)   // uint32 words in e_q
#define S_WORDS ((MAX_S * M) / 2)   // uint32 words in s_q8

// ---------------------------------------------------------------------------
__global__ void reset_kernel() {
    int t = blockIdx.x * blockDim.x + threadIdx.x;
    int stride = gridDim.x * blockDim.x;
    uint32_t* eq = reinterpret_cast<uint32_t*>(e_q);
    uint32_t* sq = reinterpret_cast<uint32_t*>(s_q8);
    for (int x = t; x < E_WORDS; x += stride) eq[x] = E_SENT;
    for (int x = t; x < S_WORDS; x += stride) sq[x] = S_SENT;
    for (int x = t; x < R; x += stride) e_cnt[x] = 0;
    for (int x = t; x < M; x += stride) s_cnt[x] = 0;
}

// ---------------------------------------------------------------------------
// Scan dense E and S (row-major [M, R]) with int4 loads; build packed lists.
__global__ void sparsify_kernel(const int* __restrict__ E, const int* __restrict__ S) {
    int t = blockIdx.x * blockDim.x + threadIdx.x;          // one int4 per thread
    const int total4 = (M * R) / 4;
    if (t >= total4) return;
    int base = t * 4;
    int i  = base >> 13;          // / R
    int j0 = base & (R - 1);      // % R   (row-aligned, R % 4 == 0)

    int4 ev = __ldg(reinterpret_cast<const int4*>(E) + t);
    int4 sv = __ldg(reinterpret_cast<const int4*>(S) + t);

    int evs[4] = {ev.x, ev.y, ev.z, ev.w};
    int svs[4] = {sv.x, sv.y, sv.z, sv.w};

    unsigned short* el = reinterpret_cast<unsigned short*>(e_q);
    unsigned short* sl = reinterpret_cast<unsigned short*>(s_q8);

    #pragma unroll
    for (int u = 0; u < 4; ++u) {
        int j = j0 + u;
        int e = evs[u];
        if (e != 0) {
            int p = atomicAdd(&e_cnt[j], 1);
            if (p < MAX_E)
                el[(size_t)(p >> 2) * (R * 4) + j * 4 + (p & 3)] =
                    (unsigned short)((i << 1) | (e - 1));
        }
        int s = svs[u];
        if (s != 0) {
            int code = (s < 0) ? (s + 2) : (s + 1);   // -2->0, -1->1, 1->2, 2->3
            int p = atomicAdd(&s_cnt[i], 1);
            if (p < MAX_S)
                sl[(size_t)(p >> 3) * (M * 8) + i * 8 + (p & 7)] =
                    (unsigned short)((j << 2) | code);
        }
    }
}

// ---------------------------------------------------------------------------
// One CTA per NB=4 batch rows; tiles stored as float4 {b0..b3}.
// smem: sc4[M+1] + sv4[R+1] (dummy slots for sentinels) = ~160 KB dynamic.
__device__ __forceinline__ void e_apply(float4& p, unsigned pk, const float4* sc4) {
    float4 c = sc4[pk >> 1];
    if (pk & 1) { c.x *= c.x; c.y *= c.y; c.z *= c.z; c.w *= c.w; }
    p.x *= c.x; p.y *= c.y; p.z *= c.z; p.w *= c.w;
}

__device__ __forceinline__ void s_apply(float4& acc, unsigned pk, const float4* sv4) {
    int code = pk & 3;
    float coeff = (float)(code - (code < 2 ? 2 : 1));  // {-2,-1,1,2}
    float4 v = sv4[pk >> 2];
    acc.x += v.x * coeff; acc.y += v.y * coeff;
    acc.z += v.z * coeff; acc.w += v.w * coeff;
}

__global__ __launch_bounds__(NT, 1) void compute_kernel(const float* __restrict__ conc,
                                                        const float* __restrict__ krate,
                                                        float* __restrict__ out) {
    extern __shared__ float4 smem4[];
    float4* sc4 = smem4;            // [M+1]
    float4* sv4 = smem4 + (M + 1);  // [R+1]

    const int b0  = blockIdx.x * NB;
    const int tid = threadIdx.x;

    const float* c0 = conc + (size_t)(b0 + 0) * M;
    const float* c1 = conc + (size_t)(b0 + 1) * M;
    const float* c2 = conc + (size_t)(b0 + 2) * M;
    const float* c3 = conc + (size_t)(b0 + 3) * M;

    #pragma unroll
    for (int u = 0; u < M / NT; ++u) {
        int m = tid + u * NT;
        float4 v;
        v.x = __ldg(&c0[m]); v.y = __ldg(&c1[m]);
        v.z = __ldg(&c2[m]); v.w = __ldg(&c3[m]);
        sc4[m] = v;
    }
    if (tid == 0) {
        sc4[M] = make_float4(1.f, 1.f, 1.f, 1.f);   // e-sentinel target
        sv4[R] = make_float4(0.f, 0.f, 0.f, 0.f);   // s-sentinel target
    }
    __syncthreads();

    // Rates: v[b,j] = k_j * prod_i c[b,i]^{E_ij}; quads of 4 independent entries.
    #pragma unroll 2
    for (int j = tid; j < R; j += NT) {
        int cnt = e_cnt[j];
        cnt = cnt < MAX_E ? cnt : MAX_E;
        int nq = (cnt + 3) >> 2;
        float kj = __ldg(&krate[j]);
        float4 p = make_float4(kj, kj, kj, kj);
        const ushort4* col = e_q + j;
        for (int q = 0; q < nq; ++q) {
            ushort4 e4 = __ldg(col + q * R);
            e_apply(p, e4.x, sc4);
            e_apply(p, e4.y, sc4);
            e_apply(p, e4.z, sc4);
            e_apply(p, e4.w, sc4);
        }
        sv4[j] = p;
    }
    __syncthreads();

    // dXdt[b,i] = sum_j v[b,j] * S_ij; octets of 8 independent entries.
    float* o0 = out + (size_t)(b0 + 0) * M;
    float* o1 = out + (size_t)(b0 + 1) * M;
    float* o2 = out + (size_t)(b0 + 2) * M;
    float* o3 = out + (size_t)(b0 + 3) * M;

    #pragma unroll
    for (int u = 0; u < M / NT; ++u) {
        int i = tid + u * NT;
        int cnt = s_cnt[i];
        cnt = cnt < MAX_S ? cnt : MAX_S;
        int ng = (cnt + 7) >> 3;
        float4 acc = make_float4(0.f, 0.f, 0.f, 0.f);
        const uint4* row = s_q8 + i;
        for (int g = 0; g < ng; ++g) {
            uint4 w = __ldg(row + g * M);
            s_apply(acc, w.x & 0xFFFFu, sv4);
            s_apply(acc, w.x >> 16,     sv4);
            s_apply(acc, w.y & 0xFFFFu, sv4);
            s_apply(acc, w.y >> 16,     sv4);
            s_apply(acc, w.z & 0xFFFFu, sv4);
            s_apply(acc, w.z >> 16,     sv4);
            s_apply(acc, w.w & 0xFFFFu, sv4);
            s_apply(acc, w.w >> 16,     sv4);
        }
        o0[i] = acc.x; o1[i] = acc.y; o2[i] = acc.z; o3[i] = acc.w;
    }
}

// ---------------------------------------------------------------------------
extern "C" void kernel_launch(void* const* d_in, const int* in_sizes, int n_in,
                              void* d_out, int out_size) {
    const float* conc = (const float*)d_in[0];   // [B, M]
    const int*   E    = (const int*)d_in[1];     // [M, R]
    const int*   S    = (const int*)d_in[2];     // [M, R]
    const float* k    = (const float*)d_in[3];   // [R]
    float*       out  = (float*)d_out;           // [B, M]

    static_assert(BATCH % NB == 0, "");

    reset_kernel<<<512, 256>>>();

    const int total4 = (M * R) / 4;
    sparsify_kernel<<<(total4 + 255) / 256, 256>>>(E, S);

    const int smem_bytes = (M + 1 + R + 1) * sizeof(float4);   // ~160 KB
    cudaFuncSetAttribute(compute_kernel, cudaFuncAttributeMaxDynamicSharedMemorySize, smem_bytes);
    compute_kernel<<<BATCH / NB, NT, smem_bytes>>>(conc, k, out);
}

// round 12
// speedup vs baseline: 2.4736x; 1.2323x over previous
#include <cuda_runtime.h>
#include <stdint.h>

// Problem dims (fixed by the reference)
#define BATCH 1024
#define M     2048
#define R     8192
#define NB    4            // batch rows per CTA
#define NT    1024         // threads per CTA (compute kernel)

#define MAX_E 32   // max nnz per reaction column of E (mean ~4.1)
#define MAX_S 64   // max nnz per metabolite row of S (mean ~16.4)

// Sentinel packs (generated in-register for slots >= cnt):
//  E entry: (i<<1)|(exp-1). Sentinel -> i = M (dummy conc slot = 1.0), exp bit 0.
//  S entry: (j<<2)|code, code: -2->0,-1->1,1->2,2->3. Sentinel -> j = R (dummy v = 0), code 2 (+1).
#define ESENT ((unsigned)(M << 1))        // 4096
#define SSENT ((unsigned)((R << 2) | 2))  // 32770

// Scratch (device globals — no allocation allowed)
__device__ int e_cnt[R];
__device__ int s_cnt[M];
__device__ ushort4 e_q[(MAX_E / 4) * R];   // quad q of column j at e_q[q*R + j]
__device__ uint4   s_q8[(MAX_S / 8) * M];  // octet g of row i at s_q8[g*M + i] (8 packed ushorts)

// ---------------------------------------------------------------------------
__global__ void reset_kernel() {       // counters only; stale list data is masked in-register
    int t = blockIdx.x * blockDim.x + threadIdx.x;
    if (t < R) e_cnt[t] = 0;
    if (t < M) s_cnt[t] = 0;
}

// ---------------------------------------------------------------------------
// Scan dense E and S (row-major [M, R]) with int4 loads; build packed lists.
__global__ void sparsify_kernel(const int* __restrict__ E, const int* __restrict__ S) {
    int t = blockIdx.x * blockDim.x + threadIdx.x;          // one int4 per thread
    const int total4 = (M * R) / 4;
    if (t >= total4) return;
    int base = t * 4;
    int i  = base >> 13;          // / R
    int j0 = base & (R - 1);      // % R   (row-aligned, R % 4 == 0)

    int4 ev = __ldg(reinterpret_cast<const int4*>(E) + t);
    int4 sv = __ldg(reinterpret_cast<const int4*>(S) + t);

    int evs[4] = {ev.x, ev.y, ev.z, ev.w};
    int svs[4] = {sv.x, sv.y, sv.z, sv.w};

    unsigned short* el = reinterpret_cast<unsigned short*>(e_q);
    unsigned short* sl = reinterpret_cast<unsigned short*>(s_q8);

    #pragma unroll
    for (int u = 0; u < 4; ++u) {
        int j = j0 + u;
        int e = evs[u];
        if (e != 0) {
            int p = atomicAdd(&e_cnt[j], 1);
            if (p < MAX_E)
                el[(size_t)(p >> 2) * (R * 4) + j * 4 + (p & 3)] =
                    (unsigned short)((i << 1) | (e - 1));
        }
        int s = svs[u];
        if (s != 0) {
            int code = (s < 0) ? (s + 2) : (s + 1);   // -2->0, -1->1, 1->2, 2->3
            int p = atomicAdd(&s_cnt[i], 1);
            if (p < MAX_S)
                sl[(size_t)(p >> 3) * (M * 8) + i * 8 + (p & 7)] =
                    (unsigned short)((j << 2) | code);
        }
    }
}

// ---------------------------------------------------------------------------
__device__ __forceinline__ void e_apply(float4& p, unsigned pk, const float4* sc4) {
    float4 c = sc4[pk >> 1];
    if (pk & 1) { c.x *= c.x; c.y *= c.y; c.z *= c.z; c.w *= c.w; }
    p.x *= c.x; p.y *= c.y; p.z *= c.z; p.w *= c.w;
}

__device__ __forceinline__ void s_apply(float4& acc, unsigned pk, const float4* sv4) {
    int code = pk & 3;
    float coeff = (float)(code - (code < 2 ? 2 : 1));  // {-2,-1,1,2}
    float4 v = sv4[pk >> 2];
    acc.x += v.x * coeff; acc.y += v.y * coeff;
    acc.z += v.z * coeff; acc.w += v.w * coeff;
}

// Apply one octet (uint4 = 8 packed entries) with in-register sentinel masking.
__device__ __forceinline__ void s_octet(float4& acc, uint4 w, int base, int cnt,
                                        const float4* sv4) {
    s_apply(acc, (base + 0 < cnt) ? (w.x & 0xFFFFu) : SSENT, sv4);
    s_apply(acc, (base + 1 < cnt) ? (w.x >> 16)     : SSENT, sv4);
    s_apply(acc, (base + 2 < cnt) ? (w.y & 0xFFFFu) : SSENT, sv4);
    s_apply(acc, (base + 3 < cnt) ? (w.y >> 16)     : SSENT, sv4);
    s_apply(acc, (base + 4 < cnt) ? (w.z & 0xFFFFu) : SSENT, sv4);
    s_apply(acc, (base + 5 < cnt) ? (w.z >> 16)     : SSENT, sv4);
    s_apply(acc, (base + 6 < cnt) ? (w.w & 0xFFFFu) : SSENT, sv4);
    s_apply(acc, (base + 7 < cnt) ? (w.w >> 16)     : SSENT, sv4);
}

// One CTA per NB=4 batch rows; tiles stored as float4 {b0..b3}.
// smem: sc4[M+1] + sv4[R+1] (dummy sentinel slots) = ~160 KB dynamic.
__global__ __launch_bounds__(NT, 1) void compute_kernel(const float* __restrict__ conc,
                                                        const float* __restrict__ krate,
                                                        float* __restrict__ out) {
    extern __shared__ float4 smem4[];
    float4* sc4 = smem4;            // [M+1]
    float4* sv4 = smem4 + (M + 1);  // [R+1]

    const int b0  = blockIdx.x * NB;
    const int tid = threadIdx.x;

    const float* c0 = conc + (size_t)(b0 + 0) * M;
    const float* c1 = conc + (size_t)(b0 + 1) * M;
    const float* c2 = conc + (size_t)(b0 + 2) * M;
    const float* c3 = conc + (size_t)(b0 + 3) * M;

    #pragma unroll
    for (int u = 0; u < M / NT; ++u) {
        int m = tid + u * NT;
        float4 v;
        v.x = __ldg(&c0[m]); v.y = __ldg(&c1[m]);
        v.z = __ldg(&c2[m]); v.w = __ldg(&c3[m]);
        sc4[m] = v;
    }
    if (tid == 0) {
        sc4[M] = make_float4(1.f, 1.f, 1.f, 1.f);   // e-sentinel target
        sv4[R] = make_float4(0.f, 0.f, 0.f, 0.f);   // s-sentinel target
    }
    __syncthreads();

    // Rates: v[b,j] = k_j * prod_i c[b,i]^{E_ij}.
    // Fixed 2 quads (8 entries) unconditionally, dynamic tail for rare cnt>8.
    #pragma unroll
    for (int u = 0; u < R / NT; ++u) {
        int j = tid + u * NT;
        int cnt = e_cnt[j];
        cnt = cnt < MAX_E ? cnt : MAX_E;
        float kj = __ldg(&krate[j]);
        const ushort4* col = e_q + j;
        ushort4 q0 = __ldg(col);
        ushort4 q1 = __ldg(col + R);
        float4 p = make_float4(kj, kj, kj, kj);
        e_apply(p, (0 < cnt) ? (unsigned)q0.x : ESENT, sc4);
        e_apply(p, (1 < cnt) ? (unsigned)q0.y : ESENT, sc4);
        e_apply(p, (2 < cnt) ? (unsigned)q0.z : ESENT, sc4);
        e_apply(p, (3 < cnt) ? (unsigned)q0.w : ESENT, sc4);
        e_apply(p, (4 < cnt) ? (unsigned)q1.x : ESENT, sc4);
        e_apply(p, (5 < cnt) ? (unsigned)q1.y : ESENT, sc4);
        e_apply(p, (6 < cnt) ? (unsigned)q1.z : ESENT, sc4);
        e_apply(p, (7 < cnt) ? (unsigned)q1.w : ESENT, sc4);
        if (cnt > 8) {
            int nq = (cnt + 3) >> 2;
            for (int q = 2; q < nq; ++q) {
                ushort4 e4 = __ldg(col + q * R);
                int base = q * 4;
                e_apply(p, (base + 0 < cnt) ? (unsigned)e4.x : ESENT, sc4);
                e_apply(p, (base + 1 < cnt) ? (unsigned)e4.y : ESENT, sc4);
                e_apply(p, (base + 2 < cnt) ? (unsigned)e4.z : ESENT, sc4);
                e_apply(p, (base + 3 < cnt) ? (unsigned)e4.w : ESENT, sc4);
            }
        }
        sv4[j] = p;
    }
    __syncthreads();

    // dXdt[b,i] = sum_j v[b,j] * S_ij.
    // Fixed 3 octets (24 entries) unconditionally, dynamic tail for rare cnt>24.
    float* o0 = out + (size_t)(b0 + 0) * M;
    float* o1 = out + (size_t)(b0 + 1) * M;
    float* o2 = out + (size_t)(b0 + 2) * M;
    float* o3 = out + (size_t)(b0 + 3) * M;

    #pragma unroll
    for (int u = 0; u < M / NT; ++u) {
        int i = tid + u * NT;
        int cnt = s_cnt[i];
        cnt = cnt < MAX_S ? cnt : MAX_S;
        const uint4* row = s_q8 + i;
        uint4 w0 = __ldg(row);
        uint4 w1 = __ldg(row + M);
        uint4 w2 = __ldg(row + 2 * M);
        float4 acc = make_float4(0.f, 0.f, 0.f, 0.f);
        s_octet(acc, w0, 0,  cnt, sv4);
        s_octet(acc, w1, 8,  cnt, sv4);
        s_octet(acc, w2, 16, cnt, sv4);
        if (cnt > 24) {
            int ng = (cnt + 7) >> 3;
            for (int g = 3; g < ng; ++g) {
                uint4 w = __ldg(row + g * M);
                s_octet(acc, w, g * 8, cnt, sv4);
            }
        }
        o0[i] = acc.x; o1[i] = acc.y; o2[i] = acc.z; o3[i] = acc.w;
    }
}

// ---------------------------------------------------------------------------
extern "C" void kernel_launch(void* const* d_in, const int* in_sizes, int n_in,
                              void* d_out, int out_size) {
    const float* conc = (const float*)d_in[0];   // [B, M]
    const int*   E    = (const int*)d_in[1];     // [M, R]
    const int*   S    = (const int*)d_in[2];     // [M, R]
    const float* k    = (const float*)d_in[3];   // [R]
    float*       out  = (float*)d_out;           // [B, M]

    static_assert(BATCH % NB == 0, "");
    static_assert(R % NT == 0 && M % NT == 0, "");

    reset_kernel<<<(R + 255) / 256, 256>>>();

    const int total4 = (M * R) / 4;
    sparsify_kernel<<<(total4 + 255) / 256, 256>>>(E, S);

    const int smem_bytes = (M + 1 + R + 1) * sizeof(float4);   // ~160 KB
    cudaFuncSetAttribute(compute_kernel, cudaFuncAttributeMaxDynamicSharedMemorySize, smem_bytes);
    compute_kernel<<<BATCH / NB, NT, smem_bytes>>>(conc, k, out);
}

// round 15
// speedup vs baseline: 2.5585x; 1.0343x over previous
#include <cuda_runtime.h>
#include <stdint.h>

// Problem dims (fixed by the reference)
#define BATCH 1024
#define M     2048
#define R     8192

#define MAX_E 32   // max nnz per reaction column of E (mean ~4.1)
#define MAX_S 64   // max nnz per metabolite row of S (mean ~16.4)

// Scratch (device globals — no allocation allowed)
__device__ int e_cnt[R];
__device__ int s_cnt[M];
__device__ unsigned short e_list[R * MAX_E];  // per-reaction: (i<<1)|(exp-1), contiguous
__device__ unsigned short s_list[M * MAX_S];  // per-metabolite: (j<<2)|code, code: -2->0,-1->1,1->2,2->3
__device__ float ct_buf[M * BATCH];           // conc transposed  [M][B]   (8 MB)
__device__ float v_buf[(size_t)R * BATCH];    // rates            [R][B]   (32 MB)
__device__ float ot_buf[M * BATCH];           // out transposed   [M][B]   (8 MB)

// ---------------------------------------------------------------------------
// Tiled transpose: in[rows][cols] -> out[cols][rows]. Optionally resets counters
// (fused so the reset costs no extra launch). blockDim = 256.
__global__ void transpose_kernel(const float* __restrict__ in, float* __restrict__ out,
                                 int rows, int cols, int do_reset) {
    __shared__ float tile[32][33];
    if (do_reset) {
        int t = (blockIdx.y * gridDim.x + blockIdx.x) * blockDim.x + threadIdx.x;
        if (t < R) e_cnt[t] = 0;
        else if (t < R + M) s_cnt[t - R] = 0;
    }
    const int c0 = blockIdx.x * 32;
    const int r0 = blockIdx.y * 32;
    const int lx = threadIdx.x & 31;
    const int ly = threadIdx.x >> 5;          // 0..7
    #pragma unroll
    for (int r = 0; r < 32; r += 8)
        tile[r + ly][lx] = in[(size_t)(r0 + r + ly) * cols + c0 + lx];
    __syncthreads();
    #pragma unroll
    for (int r = 0; r < 32; r += 8)
        out[(size_t)(c0 + r + ly) * rows + r0 + lx] = tile[lx][r + ly];
}

// ---------------------------------------------------------------------------
// Scan dense E and S (row-major [M, R]) with int4 loads; build packed lists.
__global__ void sparsify_kernel(const int* __restrict__ E, const int* __restrict__ S) {
    int t = blockIdx.x * blockDim.x + threadIdx.x;          // one int4 per thread
    const int total4 = (M * R) / 4;
    if (t >= total4) return;
    int base = t * 4;
    int i  = base >> 13;          // / R
    int j0 = base & (R - 1);      // % R   (row-aligned, R % 4 == 0)

    int4 ev = __ldg(reinterpret_cast<const int4*>(E) + t);
    int4 sv = __ldg(reinterpret_cast<const int4*>(S) + t);

    int evs[4] = {ev.x, ev.y, ev.z, ev.w};
    int svs[4] = {sv.x, sv.y, sv.z, sv.w};

    #pragma unroll
    for (int u = 0; u < 4; ++u) {
        int j = j0 + u;
        int e = evs[u];
        if (e != 0) {
            int p = atomicAdd(&e_cnt[j], 1);
            if (p < MAX_E)
                e_list[j * MAX_E + p] = (unsigned short)((i << 1) | (e - 1));
        }
        int s = svs[u];
        if (s != 0) {
            int code = (s < 0) ? (s + 2) : (s + 1);   // -2->0, -1->1, 1->2, 2->3
            int p = atomicAdd(&s_cnt[i], 1);
            if (p < MAX_S)
                s_list[i * MAX_S + p] = (unsigned short)((j << 2) | code);
        }
    }
}

// ---------------------------------------------------------------------------
// Rates: CTA j computes v[j][b] = k_j * prod_i ct[i][b]^{E_ij} for all 1024 b.
// Entry list read uniformly (broadcast); ct rows read fully coalesced from L2.
__device__ __forceinline__ void rate_apply(float4& p, unsigned pk, int b4) {
    const float4 c = *reinterpret_cast<const float4*>(ct_buf + (size_t)(pk >> 1) * BATCH + b4);
    float4 cc = c;
    if (pk & 1) { cc.x *= cc.x; cc.y *= cc.y; cc.z *= cc.z; cc.w *= cc.w; }
    p.x *= cc.x; p.y *= cc.y; p.z *= cc.z; p.w *= cc.w;
}

__global__ __launch_bounds__(256) void rate_kernel(const float* __restrict__ krate) {
    const int j  = blockIdx.x;
    const int b4 = threadIdx.x * 4;
    int cnt = e_cnt[j];
    cnt = cnt < MAX_E ? cnt : MAX_E;
    const float kj = __ldg(&krate[j]);
    float4 p = make_float4(kj, kj, kj, kj);

    const unsigned short* el = e_list + j * MAX_E;
    const uint4 w = *reinterpret_cast<const uint4*>(el);  // first 8 entries, one broadcast load
    const unsigned e8[8] = {w.x & 0xFFFFu, w.x >> 16, w.y & 0xFFFFu, w.y >> 16,
                            w.z & 0xFFFFu, w.z >> 16, w.w & 0xFFFFu, w.w >> 16};
    #pragma unroll
    for (int t = 0; t < 8; ++t)
        if (t < cnt) rate_apply(p, e8[t], b4);
    for (int t = 8; t < cnt; ++t)                     // rare tail (P ~ 3%)
        rate_apply(p, el[t], b4);

    *reinterpret_cast<float4*>(v_buf + (size_t)j * BATCH + b4) = p;
}

// ---------------------------------------------------------------------------
// Gather: CTA i computes ot[i][b] = sum_j v[j][b] * S_ij for all 1024 b.
__device__ __forceinline__ void gather_apply(float4& acc, unsigned pk, int b4) {
    const int code = pk & 3;
    const float coeff = (float)(code - (code < 2 ? 2 : 1));  // {-2,-1,1,2}
    const float4 v = *reinterpret_cast<const float4*>(v_buf + (size_t)(pk >> 2) * BATCH + b4);
    acc.x = fmaf(coeff, v.x, acc.x); acc.y = fmaf(coeff, v.y, acc.y);
    acc.z = fmaf(coeff, v.z, acc.z); acc.w = fmaf(coeff, v.w, acc.w);
}

__global__ __launch_bounds__(256) void gather_kernel() {
    const int i  = blockIdx.x;
    const int b4 = threadIdx.x * 4;
    int cnt = s_cnt[i];
    cnt = cnt < MAX_S ? cnt : MAX_S;

    const unsigned short* sl = s_list + i * MAX_S;
    const uint4 w0 = *reinterpret_cast<const uint4*>(sl);       // entries 0-7
    const uint4 w1 = *reinterpret_cast<const uint4*>(sl + 8);   // entries 8-15
    const uint4 w2 = *reinterpret_cast<const uint4*>(sl + 16);  // entries 16-23
    const unsigned s24[24] = {
        w0.x & 0xFFFFu, w0.x >> 16, w0.y & 0xFFFFu, w0.y >> 16,
        w0.z & 0xFFFFu, w0.z >> 16, w0.w & 0xFFFFu, w0.w >> 16,
        w1.x & 0xFFFFu, w1.x >> 16, w1.y & 0xFFFFu, w1.y >> 16,
        w1.z & 0xFFFFu, w1.z >> 16, w1.w & 0xFFFFu, w1.w >> 16,
        w2.x & 0xFFFFu, w2.x >> 16, w2.y & 0xFFFFu, w2.y >> 16,
        w2.z & 0xFFFFu, w2.z >> 16, w2.w & 0xFFFFu, w2.w >> 16};

    float4 acc = make_float4(0.f, 0.f, 0.f, 0.f);
    #pragma unroll
    for (int t = 0; t < 24; ++t)
        if (t < cnt) gather_apply(acc, s24[t], b4);
    for (int t = 24; t < cnt; ++t)                    // rare tail (P ~ 3%)
        gather_apply(acc, sl[t], b4);

    *reinterpret_cast<float4*>(ot_buf + (size_t)i * BATCH + b4) = acc;
}

// ---------------------------------------------------------------------------
extern "C" void kernel_launch(void* const* d_in, const int* in_sizes, int n_in,
                              void* d_out, int out_size) {
    const float* conc = (const float*)d_in[0];   // [B, M]
    const int*   E    = (const int*)d_in[1];     // [M, R]
    const int*   S    = (const int*)d_in[2];     // [M, R]
    const float* k    = (const float*)d_in[3];   // [R]
    float*       out  = (float*)d_out;           // [B, M]

    float* ct = nullptr; float* ot = nullptr;
    cudaGetSymbolAddress((void**)&ct, ct_buf);
    cudaGetSymbolAddress((void**)&ot, ot_buf);

    // 1) conc [B][M] -> ct [M][B], fused with counter reset
    {
        dim3 grid(M / 32, BATCH / 32);
        transpose_kernel<<<grid, 256>>>(conc, ct, BATCH, M, 1);
    }
    // 2) build sparse lists from dense E, S (the 128 MB HBM scan)
    {
        const int total4 = (M * R) / 4;
        sparsify_kernel<<<(total4 + 255) / 256, 256>>>(E, S);
    }
    // 3) v[j][b] = k_j * prod c^e  — coalesced over batch
    rate_kernel<<<R, 256>>>(k);
    // 4) ot[i][b] = sum_j v[j][b] * S_ij
    gather_kernel<<<M, 256>>>();
    // 5) ot [M][B] -> out [B][M]
    {
        dim3 grid(BATCH / 32, M / 32);
        transpose_kernel<<<grid, 256>>>(ot, out, M, BATCH, 0);
    }
}

// round 16
// speedup vs baseline: 2.6214x; 1.0246x over previous
#include <cuda_runtime.h>
#include <stdint.h>

// Problem dims (fixed by the reference)
#define BATCH 1024
#define M     2048
#define R     8192
#define ROWB  (BATCH * 4)   // 4096 bytes per [*, B] row

#define MAX_E 32   // max nnz per reaction column of E (mean ~4.1)
#define MAX_S 64   // max nnz per metabolite row of S (mean ~16.4)

// Scratch (device globals — no allocation allowed)
__device__ int e_cnt[R];
__device__ int s_cnt[M];
// Precomputed byte-offset entries:
//  E entry: (i << 12) | (exp-1)   -> offset into ct_buf, exp bit in bit0
//  S entry: (j << 12) | code      -> offset into v_buf, code: -2->0,-1->1,1->2,2->3
__device__ unsigned e_list[R * MAX_E];
__device__ unsigned s_list[M * MAX_S];
__device__ float ct_buf[M * BATCH];           // conc transposed  [M][B]   (8 MB)
__device__ float v_buf[(size_t)R * BATCH];    // rates            [R][B]   (32 MB)
__device__ float ot_buf[M * BATCH];           // out transposed   [M][B]   (8 MB)

// ---------------------------------------------------------------------------
// Tiled transpose: in[rows][cols] -> out[cols][rows]. Optionally resets counters.
__global__ void transpose_kernel(const float* __restrict__ in, float* __restrict__ out,
                                 int rows, int cols, int do_reset) {
    __shared__ float tile[32][33];
    if (do_reset) {
        int t = (blockIdx.y * gridDim.x + blockIdx.x) * blockDim.x + threadIdx.x;
        if (t < R) e_cnt[t] = 0;
        else if (t < R + M) s_cnt[t - R] = 0;
    }
    const int c0 = blockIdx.x * 32;
    const int r0 = blockIdx.y * 32;
    const int lx = threadIdx.x & 31;
    const int ly = threadIdx.x >> 5;          // 0..7
    #pragma unroll
    for (int r = 0; r < 32; r += 8)
        tile[r + ly][lx] = in[(size_t)(r0 + r + ly) * cols + c0 + lx];
    __syncthreads();
    #pragma unroll
    for (int r = 0; r < 32; r += 8)
        out[(size_t)(c0 + r + ly) * rows + r0 + lx] = tile[lx][r + ly];
}

// ---------------------------------------------------------------------------
// Scan dense E and S (row-major [M, R]) with int4 loads; build offset lists.
__global__ void sparsify_kernel(const int* __restrict__ E, const int* __restrict__ S) {
    int t = blockIdx.x * blockDim.x + threadIdx.x;          // one int4 per thread
    const int total4 = (M * R) / 4;
    if (t >= total4) return;
    int base = t * 4;
    int i  = base >> 13;          // / R
    int j0 = base & (R - 1);      // % R   (row-aligned, R % 4 == 0)

    int4 ev = __ldg(reinterpret_cast<const int4*>(E) + t);
    int4 sv = __ldg(reinterpret_cast<const int4*>(S) + t);

    int evs[4] = {ev.x, ev.y, ev.z, ev.w};
    int svs[4] = {sv.x, sv.y, sv.z, sv.w};

    #pragma unroll
    for (int u = 0; u < 4; ++u) {
        int j = j0 + u;
        int e = evs[u];
        if (e != 0) {
            int p = atomicAdd(&e_cnt[j], 1);
            if (p < MAX_E)
                e_list[j * MAX_E + p] = ((unsigned)i << 12) | (unsigned)(e - 1);
        }
        int s = svs[u];
        if (s != 0) {
            int code = (s < 0) ? (s + 2) : (s + 1);   // -2->0, -1->1, 1->2, 2->3
            int p = atomicAdd(&s_cnt[i], 1);
            if (p < MAX_S)
                s_list[i * MAX_S + p] = ((unsigned)j << 12) | (unsigned)code;
        }
    }
}

// ---------------------------------------------------------------------------
// Rates: CTA j computes v[j][b] = k_j * prod_i ct[i][b]^{E_ij}, 128 threads,
// two float4 chunks per thread (bytes tb and tb+2048) for 2x ILP.
__device__ __forceinline__ void rate_apply(float4& p0, float4& p1, unsigned pk,
                                           const char* ctb, int tb0) {
    const char* src = ctb + (pk & 0xFFFFF000u);
    float4 c0 = *reinterpret_cast<const float4*>(src + tb0);
    float4 c1 = *reinterpret_cast<const float4*>(src + tb0 + 2048);
    if (pk & 1) {
        c0.x *= c0.x; c0.y *= c0.y; c0.z *= c0.z; c0.w *= c0.w;
        c1.x *= c1.x; c1.y *= c1.y; c1.z *= c1.z; c1.w *= c1.w;
    }
    p0.x *= c0.x; p0.y *= c0.y; p0.z *= c0.z; p0.w *= c0.w;
    p1.x *= c1.x; p1.y *= c1.y; p1.z *= c1.z; p1.w *= c1.w;
}

__global__ __launch_bounds__(128) void rate_kernel(const float* __restrict__ krate) {
    const int j   = blockIdx.x;
    const int tb0 = threadIdx.x * 16;
    const char* ctb = reinterpret_cast<const char*>(ct_buf);
    int cnt = e_cnt[j];
    cnt = cnt < MAX_E ? cnt : MAX_E;
    const float kj = __ldg(&krate[j]);
    float4 p0 = make_float4(kj, kj, kj, kj);
    float4 p1 = p0;

    const unsigned* el = e_list + j * MAX_E;
    const uint4 w0 = *reinterpret_cast<const uint4*>(el);      // entries 0-3 (broadcast)
    const uint4 w1 = *reinterpret_cast<const uint4*>(el + 4);  // entries 4-7
    const unsigned e8[8] = {w0.x, w0.y, w0.z, w0.w, w1.x, w1.y, w1.z, w1.w};
    #pragma unroll
    for (int t = 0; t < 8; ++t)
        if (t < cnt) rate_apply(p0, p1, e8[t], ctb, tb0);
    for (int t = 8; t < cnt; ++t)                     // rare tail (P ~ 3%)
        rate_apply(p0, p1, el[t], ctb, tb0);

    char* dst = reinterpret_cast<char*>(v_buf) + (size_t)j * ROWB;
    *reinterpret_cast<float4*>(dst + tb0)        = p0;
    *reinterpret_cast<float4*>(dst + tb0 + 2048) = p1;
}

// ---------------------------------------------------------------------------
// Gather: CTA i computes ot[i][b] = sum_j v[j][b] * S_ij, 128 threads, 2x ILP.
__device__ __forceinline__ void gather_apply(float4& a0, float4& a1, unsigned pk,
                                             const char* vb, int tb0) {
    const int code = pk & 3;
    const float coeff = (float)(code - (code < 2 ? 2 : 1));  // {-2,-1,1,2}
    const char* src = vb + (pk & 0xFFFFF000u);
    const float4 v0 = *reinterpret_cast<const float4*>(src + tb0);
    const float4 v1 = *reinterpret_cast<const float4*>(src + tb0 + 2048);
    a0.x = fmaf(coeff, v0.x, a0.x); a0.y = fmaf(coeff, v0.y, a0.y);
    a0.z = fmaf(coeff, v0.z, a0.z); a0.w = fmaf(coeff, v0.w, a0.w);
    a1.x = fmaf(coeff, v1.x, a1.x); a1.y = fmaf(coeff, v1.y, a1.y);
    a1.z = fmaf(coeff, v1.z, a1.z); a1.w = fmaf(coeff, v1.w, a1.w);
}

__global__ __launch_bounds__(128) void gather_kernel() {
    const int i   = blockIdx.x;
    const int tb0 = threadIdx.x * 16;
    const char* vb = reinterpret_cast<const char*>(v_buf);
    int cnt = s_cnt[i];
    cnt = cnt < MAX_S ? cnt : MAX_S;

    const unsigned* sl = s_list + i * MAX_S;
    float4 a0 = make_float4(0.f, 0.f, 0.f, 0.f);
    float4 a1 = a0;

    // First 24 entries: three uint4 broadcast loads, predicated applies.
    const uint4 q0 = *reinterpret_cast<const uint4*>(sl);
    const uint4 q1 = *reinterpret_cast<const uint4*>(sl + 4);
    const uint4 q2 = *reinterpret_cast<const uint4*>(sl + 8);
    const uint4 q3 = *reinterpret_cast<const uint4*>(sl + 12);
    const uint4 q4 = *reinterpret_cast<const uint4*>(sl + 16);
    const uint4 q5 = *reinterpret_cast<const uint4*>(sl + 20);
    const unsigned s24[24] = {q0.x, q0.y, q0.z, q0.w, q1.x, q1.y, q1.z, q1.w,
                              q2.x, q2.y, q2.z, q2.w, q3.x, q3.y, q3.z, q3.w,
                              q4.x, q4.y, q4.z, q4.w, q5.x, q5.y, q5.z, q5.w};
    #pragma unroll
    for (int t = 0; t < 24; ++t)
        if (t < cnt) gather_apply(a0, a1, s24[t], vb, tb0);
    for (int t = 24; t < cnt; ++t)                    // rare tail (P ~ 3%)
        gather_apply(a0, a1, sl[t], vb, tb0);

    char* dst = reinterpret_cast<char*>(ot_buf) + (size_t)i * ROWB;
    *reinterpret_cast<float4*>(dst + tb0)        = a0;
    *reinterpret_cast<float4*>(dst + tb0 + 2048) = a1;
}

// ---------------------------------------------------------------------------
extern "C" void kernel_launch(void* const* d_in, const int* in_sizes, int n_in,
                              void* d_out, int out_size) {
    const float* conc = (const float*)d_in[0];   // [B, M]
    const int*   E    = (const int*)d_in[1];     // [M, R]
    const int*   S    = (const int*)d_in[2];     // [M, R]
    const float* k    = (const float*)d_in[3];   // [R]
    float*       out  = (float*)d_out;           // [B, M]

    float* ct = nullptr; float* ot = nullptr;
    cudaGetSymbolAddress((void**)&ct, ct_buf);
    cudaGetSymbolAddress((void**)&ot, ot_buf);

    // 1) conc [B][M] -> ct [M][B], fused with counter reset
    {
        dim3 grid(M / 32, BATCH / 32);
        transpose_kernel<<<grid, 256>>>(conc, ct, BATCH, M, 1);
    }
    // 2) build sparse offset lists from dense E, S (the 128 MB HBM scan)
    {
        const int total4 = (M * R) / 4;
        sparsify_kernel<<<(total4 + 255) / 256, 256>>>(E, S);
    }
    // 3) v[j][b] = k_j * prod c^e  — coalesced over batch
    rate_kernel<<<R, 128>>>(k);
    // 4) ot[i][b] = sum_j v[j][b] * S_ij
    gather_kernel<<<M, 128>>>();
    // 5) ot [M][B] -> out [B][M]
    {
        dim3 grid(BATCH / 32, M / 32);
        transpose_kernel<<<grid, 256>>>(ot, out, M, BATCH, 0);
    }
}